// round 13
// baseline (speedup 1.0000x reference)
#include <cuda_runtime.h>
#include <cuda_bf16.h>
#include <math.h>
#include <cstdint>

// Problem constants
#define NUM_ENVS   16384
#define NUM_AGENTS 16
#define IN_DIM     128
#define GCN_H      64
#define RNN_H      64
#define E_PER_G    128
#define OUT_DIM    512
#define FLAT_DIM   1024
#define N_NODES    ((size_t)NUM_ENVS * NUM_AGENTS)   // 262144

typedef unsigned long long u64;

// ---- device scratch (static) ----------------------------------------------
__device__ float g_xw  [N_NODES * GCN_H];      // x @ W_gcn
__device__ float g_h   [N_NODES * RNN_H];      // h_new fallback
__device__ float g_bias2[256];
__device__ __nv_bfloat16 g_B2hi[256 * 128];    // fused GRU weights [n][k] hi
__device__ __nv_bfloat16 g_B2lo[256 * 128];    // fused GRU weights [n][k] lo
__device__ __nv_bfloat16 g_Ahi[N_NODES * RNN_H];   // h_new bf16 hi
__device__ __nv_bfloat16 g_Alo[N_NODES * RNN_H];   // h_new bf16 lo
__device__ __nv_bfloat16 g_Whi[(size_t)OUT_DIM * FLAT_DIM]; // W_lin bf16 hi
__device__ __nv_bfloat16 g_Wlo[(size_t)OUT_DIM * FLAT_DIM]; // W_lin bf16 lo

#define FFMA2(acc, a, b) \
    asm("fma.rn.f32x2 %0, %1, %2, %0;" : "+l"(acc) : "l"(a), "l"(b))

__device__ __forceinline__ float lo32(u64 v) { return __uint_as_float((unsigned)v); }
__device__ __forceinline__ float hi32(u64 v) { return __uint_as_float((unsigned)(v >> 32)); }
__device__ __forceinline__ u64 pack2(float v) {
    u64 r; asm("mov.b64 %0, {%1, %1};" : "=l"(r) : "f"(v)); return r;
}
__device__ __forceinline__ uint32_t smem_u32(const void* p) {
    uint32_t a;
    asm("{ .reg .u64 t; cvta.to.shared.u64 t, %1; cvt.u32.u64 %0, t; }"
        : "=r"(a) : "l"(p));
    return a;
}

// ---- mma.sync helpers (base PTX; validated in R12) -------------------------
__device__ __forceinline__ void ldsm_x4(uint32_t* r, uint32_t addr) {
    asm volatile("ldmatrix.sync.aligned.m8n8.x4.shared.b16 {%0,%1,%2,%3}, [%4];"
        : "=r"(r[0]), "=r"(r[1]), "=r"(r[2]), "=r"(r[3]) : "r"(addr));
}
__device__ __forceinline__ void ldsm_x2(uint32_t* r, uint32_t addr) {
    asm volatile("ldmatrix.sync.aligned.m8n8.x2.shared.b16 {%0,%1}, [%2];"
        : "=r"(r[0]), "=r"(r[1]) : "r"(addr));
}
__device__ __forceinline__ void mma_bf16(float* d, const uint32_t* a,
                                         const uint32_t* b) {
    asm volatile("mma.sync.aligned.m16n8k16.row.col.f32.bf16.bf16.f32 "
        "{%0,%1,%2,%3}, {%4,%5,%6,%7}, {%8,%9}, {%0,%1,%2,%3};"
        : "+f"(d[0]), "+f"(d[1]), "+f"(d[2]), "+f"(d[3])
        : "r"(a[0]), "r"(a[1]), "r"(a[2]), "r"(a[3]), "r"(b[0]), "r"(b[1]));
}

// ---------------------------------------------------------------------------
// Prep: fused GRU weights as bf16 hi/lo in [n][k] layout + fp32 bias2.
// Output col n: 0..63 r, 64..127 z, 128..191 n_x, 192..255 n_h.
// k: 0..63 gcn input, 64..127 h input.  n_x|h and n_h|gcn blocks are zero.
// ---------------------------------------------------------------------------
__global__ void prep_kernel(const float* __restrict__ Wih,
                            const float* __restrict__ Whh,
                            const float* __restrict__ bih,
                            const float* __restrict__ bhh)
{
    const int n = threadIdx.x;   // 0..255
    for (int k = 0; k < 128; k++) {
        float v;
        if (k < 64) {
            v = (n < 192) ? Wih[n * 64 + k] : 0.0f;
        } else {
            int kk = k - 64;
            if      (n < 128) v = Whh[n * 64 + kk];
            else if (n < 192) v = 0.0f;
            else              v = Whh[(n - 64) * 64 + kk];
        }
        __nv_bfloat16 hi = __float2bfloat16(v);
        g_B2hi[n * 128 + k] = hi;
        g_B2lo[n * 128 + k] = __float2bfloat16(v - __bfloat162float(hi));
    }
    if (n < 128)      g_bias2[n] = bih[n] + bhh[n];
    else if (n < 192) g_bias2[n] = bih[n];
    else              g_bias2[n] = bhh[n - 64];
}

// Split W_lin [512][1024] fp32 -> bf16 hi + lo (residual)
__global__ void split_wlin_kernel(const float* __restrict__ Wlin)
{
    const int idx = blockIdx.x * 256 + threadIdx.x;
    float w = Wlin[idx];
    __nv_bfloat16 hi = __float2bfloat16(w);
    g_Whi[idx] = hi;
    g_Wlo[idx] = __float2bfloat16(w - __bfloat162float(hi));
}

// ---------------------------------------------------------------------------
// Generic GEMM (fp32 f32x2): used for xw only. Wk k-major [K][ldW].
// ---------------------------------------------------------------------------
#define GBM 128
#define GBN 64
#define GBK 32

__global__ __launch_bounds__(128)
void gemm_f32x2_kernel(const float* __restrict__ A, int lda,
                       const float* __restrict__ Wk, int ldW, int K,
                       float* __restrict__ C, int ldC)
{
    __shared__ float As [GBK][GBM + 4];
    __shared__ float Bkn[GBK][GBN + 4];

    const int tid = threadIdx.x;
    const int bm = blockIdx.x * GBM;
    const int bn = blockIdx.y * GBN;
    const int w    = tid >> 5;
    const int lane = tid & 31;
    const int ly = lane >> 4;
    const int lx = lane & 15;
    const int rbase = w * 32 + ly * 16;

    u64 acc[8][4];
    #pragma unroll
    for (int i = 0; i < 8; i++)
        #pragma unroll
        for (int j = 0; j < 4; j++) acc[i][j] = 0ull;

    const int lr = tid >> 2;
    const int lk = (tid & 3) * 4;

    for (int k0 = 0; k0 < K; k0 += GBK) {
        #pragma unroll
        for (int half = 0; half < 2; half++) {
            const int kb = k0 + half * 16;
            #pragma unroll
            for (int t = 0; t < 4; t++) {
                int row = lr + 32 * t;
                float4 v = __ldg((const float4*)(A + (size_t)(bm + row) * lda + kb + lk));
                As[half * 16 + lk + 0][row] = v.x;
                As[half * 16 + lk + 1][row] = v.y;
                As[half * 16 + lk + 2][row] = v.z;
                As[half * 16 + lk + 3][row] = v.w;
            }
            #pragma unroll
            for (int t = 0; t < 2; t++) {
                int idx = tid * 2 + t;
                int k = idx >> 4;
                int n4 = (idx & 15) * 4;
                float4 v = __ldg((const float4*)(Wk + (size_t)(kb + k) * ldW + bn + n4));
                *(float4*)&Bkn[half * 16 + k][n4] = v;
            }
        }
        __syncthreads();

        #pragma unroll
        for (int k = 0; k < GBK; k++) {
            u64 av[8], bv[4];
            #pragma unroll
            for (int i = 0; i < 8; i++)
                av[i] = *(const u64*)&As[k][rbase + 2 * i];
            #pragma unroll
            for (int j = 0; j < 4; j++)
                bv[j] = pack2(Bkn[k][lx * 4 + j]);
            #pragma unroll
            for (int i = 0; i < 8; i++)
                #pragma unroll
                for (int j = 0; j < 4; j++)
                    FFMA2(acc[i][j], av[i], bv[j]);
        }
        __syncthreads();
    }

    #pragma unroll
    for (int i = 0; i < 8; i++) {
        float4 o0, o1;
        o0.x = lo32(acc[i][0]);  o1.x = hi32(acc[i][0]);
        o0.y = lo32(acc[i][1]);  o1.y = hi32(acc[i][1]);
        o0.z = lo32(acc[i][2]);  o1.z = hi32(acc[i][2]);
        o0.w = lo32(acc[i][3]);  o1.w = hi32(acc[i][3]);
        size_t r0 = (size_t)(bm + rbase + 2 * i);
        *(float4*)(C + r0 * ldC + bn + lx * 4)       = o0;
        *(float4*)(C + (r0 + 1) * ldC + bn + lx * 4) = o1;
    }
}

// ---------------------------------------------------------------------------
// GRU mega v3: adjacency + gcn (fp32) -> bf16 hi/lo mma A-tile -> HMMA GEMM
// vs fused B2 -> in-register gate epilogue.
// Block = 64 nodes (4 envs), 256 threads (8 warps).
// Warp w owns n8 tiles {w, w+8, w+16, w+24} (cols 8w..8w+7 of each gate
// block) and all 4 m16 tiles -> gate-complete fragments.
// Dyn smem (84480 B):
//   [0]      sAhi  bf16[64][136]  17408
//   [17408]  sAlo  bf16[64][136]  17408
//   [34816]  sBhi  bf16[256][40]  20480   (aliased by sxw fp32[64][66] early)
//   [55296]  sBlo  bf16[256][40]  20480
//   [75776]  adj   f32[4][16][17]  4352
//   [80128]  deg   f32[64]          256
//   [80384]  sed   int[4][256]     4096
// ---------------------------------------------------------------------------
#define GS_AHI 0
#define GS_ALO 17408
#define GS_B   34816
#define GS_BLO 55296
#define GS_ADJ 75776
#define GS_DEG 80128
#define GS_SED 80384
#define GS_TOT 84480
#define APAD 136
#define BPAD 40

__global__ __launch_bounds__(256, 2)
void gru_mega_kernel(const float* __restrict__ xw,
                     const int* __restrict__ ei,
                     const float* __restrict__ bg,
                     const float* __restrict__ ph,
                     float* __restrict__ hout)
{
    extern __shared__ __align__(16) char gsm[];
    __nv_bfloat16* sAhi = (__nv_bfloat16*)(gsm + GS_AHI);
    __nv_bfloat16* sAlo = (__nv_bfloat16*)(gsm + GS_ALO);
    __nv_bfloat16* sBhi = (__nv_bfloat16*)(gsm + GS_B);
    __nv_bfloat16* sBlo = (__nv_bfloat16*)(gsm + GS_BLO);
    float* sxw = (float*)(gsm + GS_B);          // alias, dead before B staged
    float* adj = (float*)(gsm + GS_ADJ);
    float* deg = (float*)(gsm + GS_DEG);
    int*   sed = (int*)  (gsm + GS_SED);

    const int tid  = threadIdx.x;
    const int bm   = blockIdx.x * 64;
    const int env0 = blockIdx.x * 4;
    const int w    = tid >> 5;
    const int lane = tid & 31;

    const uint32_t aA_hi = smem_u32(sAhi);
    const uint32_t aA_lo = smem_u32(sAlo);
    const uint32_t aB_hi = smem_u32(sBhi);
    const uint32_t aB_lo = smem_u32(sBlo);

    // ---- edges + stage xw^T (fp32) + stage ph into A cols 64..127 ----------
    #pragma unroll
    for (int t = 0; t < 4; t++) {
        int idx = tid + 256 * t;
        sed[idx] = __ldg(&ei[(size_t)env0 * 2 * E_PER_G + idx]) & 15;
    }
    #pragma unroll
    for (int t = 0; t < 4; t++) {
        int idx = tid + 256 * t;                 // 0..1023
        int row = idx >> 4, q = idx & 15;
        float4 v = __ldg((const float4*)(xw + (size_t)(bm + row) * 64 + q * 4));
        sxw[(4 * q + 0) * 66 + row] = v.x;
        sxw[(4 * q + 1) * 66 + row] = v.y;
        sxw[(4 * q + 2) * 66 + row] = v.z;
        sxw[(4 * q + 3) * 66 + row] = v.w;
    }
    #pragma unroll
    for (int t = 0; t < 4; t++) {
        int idx = tid + 256 * t;                 // 0..1023
        int row = idx >> 4, q = idx & 15;        // col = 64 + 4q
        float4 v = __ldg((const float4*)(ph + (size_t)(bm + row) * 64 + 4 * q));
        float vs[4] = {v.x, v.y, v.z, v.w};
        #pragma unroll
        for (int i = 0; i < 4; i++) {
            __nv_bfloat16 hi = __float2bfloat16(vs[i]);
            sAhi[row * APAD + 64 + 4 * q + i] = hi;
            sAlo[row * APAD + 64 + 4 * q + i] =
                __float2bfloat16(vs[i] - __bfloat162float(hi));
        }
    }
    if (tid < 64) deg[tid] = 1.0f;
    #pragma unroll
    for (int t = 0; t < 5; t++) {
        int i = tid + 256 * t;
        if (i < 4 * 16 * 17) adj[i] = 0.0f;
    }
    __syncthreads();

    // ---- degrees -----------------------------------------------------------
    #pragma unroll
    for (int t = 0; t < 2; t++) {
        int eidx = tid + 256 * t;
        int e = eidx >> 7, p = eidx & 127;
        atomicAdd(&deg[e * 16 + sed[e * 256 + 128 + p]], 1.0f);
    }
    __syncthreads();

    // ---- adjacency (normalized) + self-loop --------------------------------
    #pragma unroll
    for (int t = 0; t < 2; t++) {
        int eidx = tid + 256 * t;
        int e = eidx >> 7, p = eidx & 127;
        int row = sed[e * 256 + p];
        int col = sed[e * 256 + 128 + p];
        float nm = rsqrtf(deg[e * 16 + row] * deg[e * 16 + col]);
        atomicAdd(&adj[(e * 16 + col) * 17 + row], nm);
    }
    if (tid < 64) {
        int e = tid >> 4, a = tid & 15;
        atomicAdd(&adj[(e * 16 + a) * 17 + a], 1.0f / deg[tid]);
    }
    __syncthreads();

    // ---- gcn = Adj @ xw + bias -> A cols 0..63 (bf16 hi/lo) ----------------
    {
        const int a_loc = tid & 63;
        const int jq = tid >> 6;                 // 0..3
        const int e = a_loc >> 4, a = a_loc & 15;
        float wrow[16];
        #pragma unroll
        for (int b = 0; b < 16; b++)
            wrow[b] = adj[(e * 16 + a) * 17 + b];
        #pragma unroll
        for (int jj = 0; jj < 16; jj++) {
            int j = jq * 16 + jj;
            float acc0 = __ldg(&bg[j]);
            #pragma unroll
            for (int b = 0; b < 16; b++)
                acc0 += wrow[b] * sxw[j * 66 + e * 16 + b];
            __nv_bfloat16 hi = __float2bfloat16(acc0);
            sAhi[a_loc * APAD + j] = hi;
            sAlo[a_loc * APAD + j] =
                __float2bfloat16(acc0 - __bfloat162float(hi));
        }
    }
    __syncthreads();   // sxw dead; B region free

    // ---- HMMA mainloop: K=128 in 4 chunks of 32 ----------------------------
    float acc[4][4][4];   // [m16 tile][gate][frag]
    #pragma unroll
    for (int mt = 0; mt < 4; mt++)
        #pragma unroll
        for (int gt = 0; gt < 4; gt++)
            #pragma unroll
            for (int q = 0; q < 4; q++) acc[mt][gt][q] = 0.0f;

    const int arow = (lane & 15);
    const int acol8 = (lane >> 4) * 8;
    const int brow = (lane & 7);
    const int bcol8 = ((lane >> 3) & 1) * 8;

    for (int kb = 0; kb < 128; kb += 32) {
        // stage B chunk [256 n][32 k] hi+lo (4 uint4 per thread per buffer)
        #pragma unroll
        for (int t = 0; t < 4; t++) {
            int idx = tid + 256 * t;             // 0..1023
            int n = idx >> 2, q = idx & 3;
            int soff = n * BPAD + q * 8;
            size_t goff = (size_t)n * 128 + kb + q * 8;
            *(uint4*)&sBhi[soff] = *(const uint4*)(g_B2hi + goff);
            *(uint4*)&sBlo[soff] = *(const uint4*)(g_B2lo + goff);
        }
        __syncthreads();

        #pragma unroll
        for (int ks = 0; ks < 32; ks += 16) {
            uint32_t bhi[4][2], blo[4][2];
            #pragma unroll
            for (int gt = 0; gt < 4; gt++) {
                int eoff = ((w + 8 * gt) * 8 + brow) * BPAD + ks + bcol8;
                ldsm_x2(bhi[gt], aB_hi + eoff * 2);
                ldsm_x2(blo[gt], aB_lo + eoff * 2);
            }
            #pragma unroll
            for (int mt = 0; mt < 4; mt++) {
                uint32_t ahi[4], alo[4];
                int eoff = (mt * 16 + arow) * APAD + kb + ks + acol8;
                ldsm_x4(ahi, aA_hi + eoff * 2);
                ldsm_x4(alo, aA_lo + eoff * 2);
                #pragma unroll
                for (int gt = 0; gt < 4; gt++) {
                    mma_bf16(acc[mt][gt], ahi, bhi[gt]);
                    mma_bf16(acc[mt][gt], ahi, blo[gt]);
                    mma_bf16(acc[mt][gt], alo, bhi[gt]);
                }
            }
        }
        __syncthreads();
    }

    // ---- gate epilogue (fragments are gate-complete) -----------------------
    // frag q: q=0 -> (row lane>>2,   col c0), q=1 -> (row, c0+1),
    //         q=2 -> (row+8, c0),    q=3 -> (row+8, c0+1)
    const int c0 = 8 * w + (lane & 3) * 2;
    const float br0 = __ldg(&g_bias2[c0]),       br1 = __ldg(&g_bias2[c0 + 1]);
    const float bz0 = __ldg(&g_bias2[64 + c0]),  bz1 = __ldg(&g_bias2[64 + c0 + 1]);
    const float bx0 = __ldg(&g_bias2[128 + c0]), bx1 = __ldg(&g_bias2[128 + c0 + 1]);
    const float bh0 = __ldg(&g_bias2[192 + c0]), bh1 = __ldg(&g_bias2[192 + c0 + 1]);
    #pragma unroll
    for (int mt = 0; mt < 4; mt++) {
        #pragma unroll
        for (int q = 0; q < 4; q++) {
            const int row = mt * 16 + (lane >> 2) + ((q >> 1) ? 8 : 0);
            const int c = c0 + (q & 1);
            const size_t node = (size_t)bm + row;
            float rp = acc[mt][0][q] + ((q & 1) ? br1 : br0);
            float zp = acc[mt][1][q] + ((q & 1) ? bz1 : bz0);
            float nx = acc[mt][2][q] + ((q & 1) ? bx1 : bx0);
            float nh = acc[mt][3][q] + ((q & 1) ? bh1 : bh0);
            float r = 1.0f / (1.0f + expf(-rp));
            float z = 1.0f / (1.0f + expf(-zp));
            float n = tanhf(nx + r * nh);
            float hp = __ldg(&ph[node * 64 + c]);
            float hv = (1.0f - z) * n + z * hp;
            hout[node * 64 + c] = hv;
            __nv_bfloat16 hi = __float2bfloat16(hv);
            g_Ahi[node * 64 + c] = hi;
            g_Alo[node * 64 + c] = __float2bfloat16(hv - __bfloat162float(hi));
        }
    }
}

// ---------------------------------------------------------------------------
// Logits via mma.sync bf16-split GEMM (unchanged from R12, passing).
// ---------------------------------------------------------------------------
#define LPAD 40

__global__ __launch_bounds__(256)
void logits_mma_kernel(float* __restrict__ C, const float* __restrict__ bias)
{
    __shared__ __nv_bfloat16 sAhi[128 * LPAD];
    __shared__ __nv_bfloat16 sAlo[128 * LPAD];
    __shared__ __nv_bfloat16 sBhi[128 * LPAD];
    __shared__ __nv_bfloat16 sBlo[128 * LPAD];

    const int tid  = threadIdx.x;
    const int wid  = tid >> 5;
    const int lane = tid & 31;
    const int wm = wid >> 1;
    const int wn = wid & 1;
    const int bm0 = blockIdx.x * 128;
    const int bn0 = blockIdx.y * 128;

    const uint32_t aAhi = smem_u32(sAhi);
    const uint32_t aAlo = smem_u32(sAlo);
    const uint32_t aBhi = smem_u32(sBhi);
    const uint32_t aBlo = smem_u32(sBlo);

    float acc[2][8][4];
    #pragma unroll
    for (int mt = 0; mt < 2; mt++)
        #pragma unroll
        for (int nt = 0; nt < 8; nt++)
            #pragma unroll
            for (int q = 0; q < 4; q++) acc[mt][nt][q] = 0.0f;

    const int arow = (lane & 15);
    const int acol8 = (lane >> 4) * 8;
    const int brow = (lane & 7);
    const int bcol8 = ((lane >> 3) & 1) * 8;

    for (int kb = 0; kb < FLAT_DIM; kb += 32) {
        #pragma unroll
        for (int t = 0; t < 2; t++) {
            int idx = tid + 256 * t;
            int row = idx >> 2, q = idx & 3;
            int soff = row * LPAD + q * 8;
            size_t ga = (size_t)(bm0 + row) * FLAT_DIM + kb + q * 8;
            size_t gb = (size_t)(bn0 + row) * FLAT_DIM + kb + q * 8;
            *(uint4*)&sAhi[soff] = __ldg((const uint4*)(g_Ahi + ga));
            *(uint4*)&sAlo[soff] = __ldg((const uint4*)(g_Alo + ga));
            *(uint4*)&sBhi[soff] = __ldg((const uint4*)(g_Whi + gb));
            *(uint4*)&sBlo[soff] = __ldg((const uint4*)(g_Wlo + gb));
        }
        __syncthreads();

        #pragma unroll
        for (int ks = 0; ks < 32; ks += 16) {
            uint32_t ahi[2][4], alo[2][4];
            #pragma unroll
            for (int mt = 0; mt < 2; mt++) {
                int eoff = (wm * 32 + mt * 16 + arow) * LPAD + ks + acol8;
                ldsm_x4(ahi[mt], aAhi + eoff * 2);
                ldsm_x4(alo[mt], aAlo + eoff * 2);
            }
            #pragma unroll
            for (int nt = 0; nt < 8; nt++) {
                int eoff = (wn * 64 + nt * 8 + brow) * LPAD + ks + bcol8;
                uint32_t bhi[2], blo[2];
                ldsm_x2(bhi, aBhi + eoff * 2);
                ldsm_x2(blo, aBlo + eoff * 2);
                #pragma unroll
                for (int mt = 0; mt < 2; mt++) {
                    mma_bf16(acc[mt][nt], ahi[mt], bhi);
                    mma_bf16(acc[mt][nt], ahi[mt], blo);
                    mma_bf16(acc[mt][nt], alo[mt], bhi);
                }
            }
        }
        __syncthreads();
    }

    const int erow = lane >> 2;
    const int ecol = (lane & 3) * 2;
    #pragma unroll
    for (int mt = 0; mt < 2; mt++) {
        #pragma unroll
        for (int nt = 0; nt < 8; nt++) {
            int col = bn0 + wn * 64 + nt * 8 + ecol;
            float b0 = __ldg(&bias[col]);
            float b1 = __ldg(&bias[col + 1]);
            size_t r0 = (size_t)(bm0 + wm * 32 + mt * 16 + erow);
            float2 v0 = make_float2(acc[mt][nt][0] + b0, acc[mt][nt][1] + b1);
            float2 v1 = make_float2(acc[mt][nt][2] + b0, acc[mt][nt][3] + b1);
            *(float2*)(C + r0 * OUT_DIM + col)       = v0;
            *(float2*)(C + (r0 + 8) * OUT_DIM + col) = v1;
        }
    }
}

// ---------------------------------------------------------------------------
extern "C" void kernel_launch(void* const* d_in, const int* in_sizes, int n_in,
                              void* d_out, int out_size)
{
    const float* x    = (const float*)d_in[0];
    const int*   ei   = (const int*)d_in[1];
    const float* ph   = (const float*)d_in[2];
    const float* Wg   = (const float*)d_in[3];     // [128][64] k-major
    const float* bg   = (const float*)d_in[4];
    const float* Wih  = (const float*)d_in[5];
    const float* Whh  = (const float*)d_in[6];
    const float* bih  = (const float*)d_in[7];
    const float* bhh  = (const float*)d_in[8];
    const float* Wlin = (const float*)d_in[9];
    const float* blin = (const float*)d_in[10];

    float* out    = (float*)d_out;
    float* logits = out;

    static float *p_xw = nullptr, *p_h = nullptr;
    static bool attr_done = false;
    if (!p_xw) {
        cudaGetSymbolAddress((void**)&p_xw, g_xw);
        cudaGetSymbolAddress((void**)&p_h,  g_h);
    }
    if (!attr_done) {
        cudaFuncSetAttribute(gru_mega_kernel,
                             cudaFuncAttributeMaxDynamicSharedMemorySize, GS_TOT);
        attr_done = true;
    }

    const long long need = (long long)NUM_ENVS * (OUT_DIM + FLAT_DIM);
    float* hout = ((long long)out_size >= need)
                      ? out + (size_t)NUM_ENVS * OUT_DIM
                      : p_h;

    prep_kernel<<<1, 256>>>(Wih, Whh, bih, bhh);
    split_wlin_kernel<<<(OUT_DIM * FLAT_DIM) / 256, 256>>>(Wlin);

    // 1) xw = x @ W_gcn
    {
        dim3 g(N_NODES / GBM, 1);
        gemm_f32x2_kernel<<<g, 128>>>(x, IN_DIM, Wg, GCN_H, IN_DIM,
                                      p_xw, GCN_H);
    }

    // 2+3+4) scatter + GRU (HMMA) + gates fused
    gru_mega_kernel<<<N_NODES / 64, 256, GS_TOT>>>(p_xw, ei, bg, ph, hout);

    // 5) logits via mma.sync bf16-split GEMM
    {
        dim3 g(NUM_ENVS / 128, OUT_DIM / 128);
        logits_mma_kernel<<<g, 256>>>(logits, blin);
    }
}

// round 14
// speedup vs baseline: 1.2930x; 1.2930x over previous
#include <cuda_runtime.h>
#include <cuda_bf16.h>
#include <math.h>
#include <cstdint>

// Problem constants
#define NUM_ENVS   16384
#define NUM_AGENTS 16
#define IN_DIM     128
#define GCN_H      64
#define RNN_H      64
#define E_PER_G    128
#define OUT_DIM    512
#define FLAT_DIM   1024
#define N_NODES    ((size_t)NUM_ENVS * NUM_AGENTS)   // 262144

typedef unsigned long long u64;

// ---- device scratch (static) ----------------------------------------------
__device__ float g_xw  [N_NODES * GCN_H];      // x @ W_gcn (fp32)
__device__ float g_h   [N_NODES * RNN_H];      // h_new fallback
__device__ float g_bias2[256];
__device__ __nv_bfloat16 g_B2hi[256 * 128];    // fused GRU weights [n][k] hi
__device__ __nv_bfloat16 g_B2lo[256 * 128];    // fused GRU weights [n][k] lo
__device__ __nv_bfloat16 g_Wghi[64 * 128];     // W_gcn^T [n][k] hi
__device__ __nv_bfloat16 g_Wglo[64 * 128];     // W_gcn^T [n][k] lo
__device__ __nv_bfloat16 g_Ahi[N_NODES * RNN_H];   // h_new bf16 hi
__device__ __nv_bfloat16 g_Alo[N_NODES * RNN_H];   // h_new bf16 lo
__device__ __nv_bfloat16 g_Whi[(size_t)OUT_DIM * FLAT_DIM]; // W_lin bf16 hi
__device__ __nv_bfloat16 g_Wlo[(size_t)OUT_DIM * FLAT_DIM]; // W_lin bf16 lo

__device__ __forceinline__ uint32_t smem_u32(const void* p) {
    uint32_t a;
    asm("{ .reg .u64 t; cvta.to.shared.u64 t, %1; cvt.u32.u64 %0, t; }"
        : "=r"(a) : "l"(p));
    return a;
}

// ---- mma.sync / ldmatrix / cp.async helpers (base PTX; validated R12/13) ---
__device__ __forceinline__ void ldsm_x4(uint32_t* r, uint32_t addr) {
    asm volatile("ldmatrix.sync.aligned.m8n8.x4.shared.b16 {%0,%1,%2,%3}, [%4];"
        : "=r"(r[0]), "=r"(r[1]), "=r"(r[2]), "=r"(r[3]) : "r"(addr));
}
__device__ __forceinline__ void ldsm_x2(uint32_t* r, uint32_t addr) {
    asm volatile("ldmatrix.sync.aligned.m8n8.x2.shared.b16 {%0,%1}, [%2];"
        : "=r"(r[0]), "=r"(r[1]) : "r"(addr));
}
__device__ __forceinline__ void mma_bf16(float* d, const uint32_t* a,
                                         const uint32_t* b) {
    asm volatile("mma.sync.aligned.m16n8k16.row.col.f32.bf16.bf16.f32 "
        "{%0,%1,%2,%3}, {%4,%5,%6,%7}, {%8,%9}, {%0,%1,%2,%3};"
        : "+f"(d[0]), "+f"(d[1]), "+f"(d[2]), "+f"(d[3])
        : "r"(a[0]), "r"(a[1]), "r"(a[2]), "r"(a[3]), "r"(b[0]), "r"(b[1]));
}
__device__ __forceinline__ void cp16(uint32_t dst, const void* src) {
    asm volatile("cp.async.ca.shared.global [%0], [%1], 16;"
                 :: "r"(dst), "l"(src));
}
#define CP_COMMIT() asm volatile("cp.async.commit_group;" ::: "memory")
#define CP_WAIT(n)  asm volatile("cp.async.wait_group %0;" :: "n"(n) : "memory")

__device__ __forceinline__ uint32_t pack_bf2(float a, float b) {
    __nv_bfloat16 ha = __float2bfloat16(a);
    __nv_bfloat16 hb = __float2bfloat16(b);
    return (uint32_t)__bfloat16_as_ushort(ha)
         | ((uint32_t)__bfloat16_as_ushort(hb) << 16);
}

// ---------------------------------------------------------------------------
// Prep (parallel, 128 blocks): fused GRU weights bf16 hi/lo [n][k] + bias2.
// cols n: 0..63 r, 64..127 z, 128..191 n_x, 192..255 n_h. k: [gcn|h].
// ---------------------------------------------------------------------------
__global__ void prep_kernel(const float* __restrict__ Wih,
                            const float* __restrict__ Whh,
                            const float* __restrict__ bih,
                            const float* __restrict__ bhh)
{
    const int idx = blockIdx.x * 256 + threadIdx.x;   // 0..32767
    const int n = idx >> 7, k = idx & 127;
    float v;
    if (k < 64) {
        v = (n < 192) ? Wih[n * 64 + k] : 0.0f;
    } else {
        int kk = k - 64;
        if      (n < 128) v = Whh[n * 64 + kk];
        else if (n < 192) v = 0.0f;
        else              v = Whh[(n - 64) * 64 + kk];
    }
    __nv_bfloat16 hi = __float2bfloat16(v);
    g_B2hi[idx] = hi;
    g_B2lo[idx] = __float2bfloat16(v - __bfloat162float(hi));
    if (k == 0) {
        if (n < 128)      g_bias2[n] = bih[n] + bhh[n];
        else if (n < 192) g_bias2[n] = bih[n];
        else              g_bias2[n] = bhh[n - 64];
    }
}

// W_gcn [128][64] k-major -> bf16 hi/lo [64 n][128 k]
__global__ void transpose_wg_kernel(const float* __restrict__ Wg)
{
    const int idx = blockIdx.x * 256 + threadIdx.x;   // 0..8191
    const int n = idx >> 7, k = idx & 127;
    float v = Wg[k * 64 + n];
    __nv_bfloat16 hi = __float2bfloat16(v);
    g_Wghi[idx] = hi;
    g_Wglo[idx] = __float2bfloat16(v - __bfloat162float(hi));
}

// Split W_lin [512][1024] fp32 -> bf16 hi + lo (residual)
__global__ void split_wlin_kernel(const float* __restrict__ Wlin)
{
    const int idx = blockIdx.x * 256 + threadIdx.x;
    float w = Wlin[idx];
    __nv_bfloat16 hi = __float2bfloat16(w);
    g_Whi[idx] = hi;
    g_Wlo[idx] = __float2bfloat16(w - __bfloat162float(hi));
}

// ---------------------------------------------------------------------------
// xw = x @ W_gcn via HMMA bf16-split. Block = 128 rows x 64 N, K=128.
// A (fp32 x) split to hi/lo in registers during staging. B staged once.
// 8 warps: warp wid owns m16 tile (rows wid*16..+15), all 8 n8 tiles.
// ---------------------------------------------------------------------------
#define XAPAD 40
#define XBPAD 136

__global__ __launch_bounds__(256)
void xw_mma_kernel(const float* __restrict__ x, float* __restrict__ xwout)
{
    __shared__ __nv_bfloat16 sAhi[128 * XAPAD];
    __shared__ __nv_bfloat16 sAlo[128 * XAPAD];
    __shared__ __nv_bfloat16 sBhi[64 * XBPAD];
    __shared__ __nv_bfloat16 sBlo[64 * XBPAD];

    const int tid  = threadIdx.x;
    const int wid  = tid >> 5;
    const int lane = tid & 31;
    const int bm0 = blockIdx.x * 128;

    const uint32_t aAhi = smem_u32(sAhi);
    const uint32_t aAlo = smem_u32(sAlo);
    const uint32_t aBhi = smem_u32(sBhi);
    const uint32_t aBlo = smem_u32(sBlo);

    // stage B once (64 n x 128 k, hi+lo)
    #pragma unroll
    for (int t = 0; t < 4; t++) {
        int idx = tid + 256 * t;                 // 0..1023
        int row = idx >> 4, q = idx & 15;        // 16 x 16B per row
        *(uint4*)&sBhi[row * XBPAD + q * 8] = *(const uint4*)(g_Wghi + row * 128 + q * 8);
        *(uint4*)&sBlo[row * XBPAD + q * 8] = *(const uint4*)(g_Wglo + row * 128 + q * 8);
    }

    float acc[8][4];
    #pragma unroll
    for (int nt = 0; nt < 8; nt++)
        #pragma unroll
        for (int q = 0; q < 4; q++) acc[nt][q] = 0.0f;

    const int arow = (lane & 15);
    const int acol8 = (lane >> 4) * 8;
    const int brow = (lane & 7);
    const int bcol8 = ((lane >> 3) & 1) * 8;

    for (int kb = 0; kb < 128; kb += 32) {
        // stage A chunk: 128 rows x 32 fp32 -> bf16 hi/lo
        #pragma unroll
        for (int t = 0; t < 4; t++) {
            int idx = tid + 256 * t;             // 0..1023
            int row = idx >> 3, q = idx & 7;     // 8 x float4 per row
            float4 v = __ldg((const float4*)(x + (size_t)(bm0 + row) * 128 + kb + q * 4));
            int base = row * XAPAD + q * 4;
            *(uint32_t*)&sAhi[base]     = pack_bf2(v.x, v.y);
            *(uint32_t*)&sAhi[base + 2] = pack_bf2(v.z, v.w);
            float rx = v.x - __bfloat162float(__float2bfloat16(v.x));
            float ry = v.y - __bfloat162float(__float2bfloat16(v.y));
            float rz = v.z - __bfloat162float(__float2bfloat16(v.z));
            float rw = v.w - __bfloat162float(__float2bfloat16(v.w));
            *(uint32_t*)&sAlo[base]     = pack_bf2(rx, ry);
            *(uint32_t*)&sAlo[base + 2] = pack_bf2(rz, rw);
        }
        __syncthreads();

        #pragma unroll
        for (int ks = 0; ks < 32; ks += 16) {
            uint32_t ahi[4], alo[4];
            int eoffA = (wid * 16 + arow) * XAPAD + ks + acol8;
            ldsm_x4(ahi, aAhi + eoffA * 2);
            ldsm_x4(alo, aAlo + eoffA * 2);
            #pragma unroll
            for (int nt = 0; nt < 8; nt++) {
                int eoffB = (nt * 8 + brow) * XBPAD + kb + ks + bcol8;
                uint32_t bhi[2], blo[2];
                ldsm_x2(bhi, aBhi + eoffB * 2);
                ldsm_x2(blo, aBlo + eoffB * 2);
                mma_bf16(acc[nt], ahi, bhi);
                mma_bf16(acc[nt], ahi, blo);
                mma_bf16(acc[nt], alo, bhi);
            }
        }
        __syncthreads();
    }

    const int erow = lane >> 2;
    const int ecol = (lane & 3) * 2;
    #pragma unroll
    for (int nt = 0; nt < 8; nt++) {
        int col = nt * 8 + ecol;
        size_t r0 = (size_t)(bm0 + wid * 16 + erow);
        *(float2*)(xwout + r0 * 64 + col)       = make_float2(acc[nt][0], acc[nt][1]);
        *(float2*)(xwout + (r0 + 8) * 64 + col) = make_float2(acc[nt][2], acc[nt][3]);
    }
}

// ---------------------------------------------------------------------------
// GRU mega v3.1: adjacency + gcn (fp32) -> bf16 hi/lo A-tile -> HMMA GEMM
// vs fused B2 -> in-register gate epilogue. B chunk 0 prefetched via cp.async
// during the prologue (sxw has its own region now).
// Dyn smem (101376 B):
//   [0]      sAhi bf16[64][136] 17408    [17408] sAlo 17408
//   [34816]  sBhi bf16[256][40] 20480    [55296] sBlo 20480
//   [75776]  sxw  f32[64][66]   16896
//   [92672]  adj  f32[4][16][17] 4352    [97024] deg f32[64] 256
//   [97280]  sed  int[4][256]   4096
// ---------------------------------------------------------------------------
#define GS_AHI 0
#define GS_ALO 17408
#define GS_BHI 34816
#define GS_BLO 55296
#define GS_SXW 75776
#define GS_ADJ 92672
#define GS_DEG 97024
#define GS_SED 97280
#define GS_TOT 101376
#define APAD 136
#define BPAD 40

__global__ __launch_bounds__(256, 2)
void gru_mega_kernel(const float* __restrict__ xw,
                     const int* __restrict__ ei,
                     const float* __restrict__ bg,
                     const float* __restrict__ ph,
                     float* __restrict__ hout)
{
    extern __shared__ __align__(16) char gsm[];
    __nv_bfloat16* sAhi = (__nv_bfloat16*)(gsm + GS_AHI);
    __nv_bfloat16* sAlo = (__nv_bfloat16*)(gsm + GS_ALO);
    __nv_bfloat16* sBhi = (__nv_bfloat16*)(gsm + GS_BHI);
    __nv_bfloat16* sBlo = (__nv_bfloat16*)(gsm + GS_BLO);
    float* sxw = (float*)(gsm + GS_SXW);
    float* adj = (float*)(gsm + GS_ADJ);
    float* deg = (float*)(gsm + GS_DEG);
    int*   sed = (int*)  (gsm + GS_SED);

    const int tid  = threadIdx.x;
    const int bm   = blockIdx.x * 64;
    const int env0 = blockIdx.x * 4;
    const int w    = tid >> 5;
    const int lane = tid & 31;

    const uint32_t gsb  = smem_u32(gsm);
    const uint32_t aA_hi = gsb + GS_AHI;
    const uint32_t aA_lo = gsb + GS_ALO;
    const uint32_t aB_hi = gsb + GS_BHI;
    const uint32_t aB_lo = gsb + GS_BLO;

    // ---- prefetch B chunk 0 (hi+lo) via cp.async ---------------------------
    #pragma unroll
    for (int t = 0; t < 4; t++) {
        int idx = tid + 256 * t;                 // 0..1023
        int n = idx >> 2, q = idx & 3;
        uint32_t so = n * (BPAD * 2) + q * 16;
        cp16(aB_hi + so, g_B2hi + (size_t)n * 128 + q * 8);
        cp16(aB_lo + so, g_B2lo + (size_t)n * 128 + q * 8);
    }
    CP_COMMIT();

    // ---- edges + stage xw^T (fp32) + stage ph into A cols 64..127 ----------
    #pragma unroll
    for (int t = 0; t < 4; t++) {
        int idx = tid + 256 * t;
        sed[idx] = __ldg(&ei[(size_t)env0 * 2 * E_PER_G + idx]) & 15;
    }
    #pragma unroll
    for (int t = 0; t < 4; t++) {
        int idx = tid + 256 * t;                 // 0..1023
        int row = idx >> 4, q = idx & 15;
        float4 v = __ldg((const float4*)(xw + (size_t)(bm + row) * 64 + q * 4));
        sxw[(4 * q + 0) * 66 + row] = v.x;
        sxw[(4 * q + 1) * 66 + row] = v.y;
        sxw[(4 * q + 2) * 66 + row] = v.z;
        sxw[(4 * q + 3) * 66 + row] = v.w;
    }
    #pragma unroll
    for (int t = 0; t < 4; t++) {
        int idx = tid + 256 * t;                 // 0..1023
        int row = idx >> 4, q = idx & 15;        // col = 64 + 4q
        float4 v = __ldg((const float4*)(ph + (size_t)(bm + row) * 64 + 4 * q));
        int base = row * APAD + 64 + 4 * q;
        *(uint32_t*)&sAhi[base]     = pack_bf2(v.x, v.y);
        *(uint32_t*)&sAhi[base + 2] = pack_bf2(v.z, v.w);
        float rx = v.x - __bfloat162float(__float2bfloat16(v.x));
        float ry = v.y - __bfloat162float(__float2bfloat16(v.y));
        float rz = v.z - __bfloat162float(__float2bfloat16(v.z));
        float rw = v.w - __bfloat162float(__float2bfloat16(v.w));
        *(uint32_t*)&sAlo[base]     = pack_bf2(rx, ry);
        *(uint32_t*)&sAlo[base + 2] = pack_bf2(rz, rw);
    }
    if (tid < 64) deg[tid] = 1.0f;
    #pragma unroll
    for (int t = 0; t < 5; t++) {
        int i = tid + 256 * t;
        if (i < 4 * 16 * 17) adj[i] = 0.0f;
    }
    __syncthreads();

    // ---- degrees -----------------------------------------------------------
    #pragma unroll
    for (int t = 0; t < 2; t++) {
        int eidx = tid + 256 * t;
        int e = eidx >> 7, p = eidx & 127;
        atomicAdd(&deg[e * 16 + sed[e * 256 + 128 + p]], 1.0f);
    }
    __syncthreads();

    // ---- adjacency (normalized) + self-loop --------------------------------
    #pragma unroll
    for (int t = 0; t < 2; t++) {
        int eidx = tid + 256 * t;
        int e = eidx >> 7, p = eidx & 127;
        int row = sed[e * 256 + p];
        int col = sed[e * 256 + 128 + p];
        float nm = rsqrtf(deg[e * 16 + row] * deg[e * 16 + col]);
        atomicAdd(&adj[(e * 16 + col) * 17 + row], nm);
    }
    if (tid < 64) {
        int e = tid >> 4, a = tid & 15;
        atomicAdd(&adj[(e * 16 + a) * 17 + a], 1.0f / deg[tid]);
    }
    __syncthreads();

    // ---- gcn = Adj @ xw + bias -> A cols 0..63 (bf16 hi/lo) ----------------
    {
        const int a_loc = tid & 63;
        const int jq = tid >> 6;                 // 0..3
        const int e = a_loc >> 4, a = a_loc & 15;
        float wrow[16];
        #pragma unroll
        for (int b = 0; b < 16; b++)
            wrow[b] = adj[(e * 16 + a) * 17 + b];
        #pragma unroll
        for (int jj = 0; jj < 16; jj++) {
            int j = jq * 16 + jj;
            float acc0 = __ldg(&bg[j]);
            #pragma unroll
            for (int b = 0; b < 16; b++)
                acc0 += wrow[b] * sxw[j * 66 + e * 16 + b];
            __nv_bfloat16 hi = __float2bfloat16(acc0);
            sAhi[a_loc * APAD + j] = hi;
            sAlo[a_loc * APAD + j] =
                __float2bfloat16(acc0 - __bfloat162float(hi));
        }
    }

    // ---- HMMA mainloop: K=128 in 4 chunks of 32 ----------------------------
    float acc[4][4][4];   // [m16 tile][gate][frag]
    #pragma unroll
    for (int mt = 0; mt < 4; mt++)
        #pragma unroll
        for (int gt = 0; gt < 4; gt++)
            #pragma unroll
            for (int q = 0; q < 4; q++) acc[mt][gt][q] = 0.0f;

    const int arow = (lane & 15);
    const int acol8 = (lane >> 4) * 8;
    const int brow = (lane & 7);
    const int bcol8 = ((lane >> 3) & 1) * 8;

    for (int kb = 0; kb < 128; kb += 32) {
        if (kb == 0) {
            CP_WAIT(0);
        } else {
            #pragma unroll
            for (int t = 0; t < 4; t++) {
                int idx = tid + 256 * t;         // 0..1023
                int n = idx >> 2, q = idx & 3;
                int soff = n * BPAD + q * 8;
                size_t goff = (size_t)n * 128 + kb + q * 8;
                *(uint4*)&sBhi[soff] = *(const uint4*)(g_B2hi + goff);
                *(uint4*)&sBlo[soff] = *(const uint4*)(g_B2lo + goff);
            }
        }
        __syncthreads();

        #pragma unroll
        for (int ks = 0; ks < 32; ks += 16) {
            uint32_t bhi[4][2], blo[4][2];
            #pragma unroll
            for (int gt = 0; gt < 4; gt++) {
                int eoff = ((w + 8 * gt) * 8 + brow) * BPAD + ks + bcol8;
                ldsm_x2(bhi[gt], aB_hi + eoff * 2);
                ldsm_x2(blo[gt], aB_lo + eoff * 2);
            }
            #pragma unroll
            for (int mt = 0; mt < 4; mt++) {
                uint32_t ahi[4], alo[4];
                int eoff = (mt * 16 + arow) * APAD + kb + ks + acol8;
                ldsm_x4(ahi, aA_hi + eoff * 2);
                ldsm_x4(alo, aA_lo + eoff * 2);
                #pragma unroll
                for (int gt = 0; gt < 4; gt++) {
                    mma_bf16(acc[mt][gt], ahi, bhi[gt]);
                    mma_bf16(acc[mt][gt], ahi, blo[gt]);
                    mma_bf16(acc[mt][gt], alo, bhi[gt]);
                }
            }
        }
        __syncthreads();
    }

    // ---- gate epilogue (fragments are gate-complete) -----------------------
    const int c0 = 8 * w + (lane & 3) * 2;
    const float br0 = __ldg(&g_bias2[c0]),       br1 = __ldg(&g_bias2[c0 + 1]);
    const float bz0 = __ldg(&g_bias2[64 + c0]),  bz1 = __ldg(&g_bias2[64 + c0 + 1]);
    const float bx0 = __ldg(&g_bias2[128 + c0]), bx1 = __ldg(&g_bias2[128 + c0 + 1]);
    const float bh0 = __ldg(&g_bias2[192 + c0]), bh1 = __ldg(&g_bias2[192 + c0 + 1]);
    #pragma unroll
    for (int mt = 0; mt < 4; mt++) {
        #pragma unroll
        for (int q = 0; q < 4; q++) {
            const int row = mt * 16 + (lane >> 2) + ((q >> 1) ? 8 : 0);
            const int c = c0 + (q & 1);
            const size_t node = (size_t)bm + row;
            float rp = acc[mt][0][q] + ((q & 1) ? br1 : br0);
            float zp = acc[mt][1][q] + ((q & 1) ? bz1 : bz0);
            float nx = acc[mt][2][q] + ((q & 1) ? bx1 : bx0);
            float nh = acc[mt][3][q] + ((q & 1) ? bh1 : bh0);
            float r = 1.0f / (1.0f + expf(-rp));
            float z = 1.0f / (1.0f + expf(-zp));
            float n = tanhf(nx + r * nh);
            float hp = __ldg(&ph[node * 64 + c]);
            float hv = (1.0f - z) * n + z * hp;
            hout[node * 64 + c] = hv;
            __nv_bfloat16 hi = __float2bfloat16(hv);
            g_Ahi[node * 64 + c] = hi;
            g_Alo[node * 64 + c] = __float2bfloat16(hv - __bfloat162float(hi));
        }
    }
}

// ---------------------------------------------------------------------------
// Logits via mma.sync bf16-split GEMM with 2-stage cp.async pipeline.
// Block 128M x 128N; K=1024 in 32 chunks. Dyn smem 81920 B (2 stages x
// {Ahi,Alo,Bhi,Blo} of 128x40 bf16 = 10240 B each).
// ---------------------------------------------------------------------------
#define LPAD 40
#define LG_STG 40960
#define LO_AHI 0
#define LO_ALO 10240
#define LO_BHI 20480
#define LO_BLO 30720
#define LG_TOT 81920

__global__ __launch_bounds__(256)
void logits_mma_kernel(float* __restrict__ C, const float* __restrict__ bias)
{
    extern __shared__ __align__(16) char lsm[];
    const uint32_t sbase = smem_u32(lsm);

    const int tid  = threadIdx.x;
    const int wid  = tid >> 5;
    const int lane = tid & 31;
    const int wm = wid >> 1;
    const int wn = wid & 1;
    const int bm0 = blockIdx.x * 128;
    const int bn0 = blockIdx.y * 128;

    float acc[2][8][4];
    #pragma unroll
    for (int mt = 0; mt < 2; mt++)
        #pragma unroll
        for (int nt = 0; nt < 8; nt++)
            #pragma unroll
            for (int q = 0; q < 4; q++) acc[mt][nt][q] = 0.0f;

    const int arow = (lane & 15);
    const int acol8 = (lane >> 4) * 8;
    const int brow = (lane & 7);
    const int bcol8 = ((lane >> 3) & 1) * 8;

    // async stage helper (inlined twice)
    const int srow = tid >> 2;          // 0..63 (with t loop covers 128)
    const int sq   = tid & 3;

    // preload stage 0, kb=0
    {
        uint32_t base = sbase;
        #pragma unroll
        for (int t = 0; t < 2; t++) {
            int row = srow + 64 * t;
            uint32_t so = row * (LPAD * 2) + sq * 16;
            size_t ga = (size_t)(bm0 + row) * FLAT_DIM + sq * 8;
            size_t gb = (size_t)(bn0 + row) * FLAT_DIM + sq * 8;
            cp16(base + LO_AHI + so, g_Ahi + ga);
            cp16(base + LO_ALO + so, g_Alo + ga);
            cp16(base + LO_BHI + so, g_Whi + gb);
            cp16(base + LO_BLO + so, g_Wlo + gb);
        }
        CP_COMMIT();
    }

    for (int i = 0; i < 32; i++) {
        if (i + 1 < 32) {
            uint32_t base = sbase + ((i + 1) & 1) * LG_STG;
            int kbn = (i + 1) * 32;
            #pragma unroll
            for (int t = 0; t < 2; t++) {
                int row = srow + 64 * t;
                uint32_t so = row * (LPAD * 2) + sq * 16;
                size_t ga = (size_t)(bm0 + row) * FLAT_DIM + kbn + sq * 8;
                size_t gb = (size_t)(bn0 + row) * FLAT_DIM + kbn + sq * 8;
                cp16(base + LO_AHI + so, g_Ahi + ga);
                cp16(base + LO_ALO + so, g_Alo + ga);
                cp16(base + LO_BHI + so, g_Whi + gb);
                cp16(base + LO_BLO + so, g_Wlo + gb);
            }
            CP_COMMIT();
            CP_WAIT(1);
        } else {
            CP_WAIT(0);
        }
        __syncthreads();

        const uint32_t b = sbase + (i & 1) * LG_STG;
        #pragma unroll
        for (int ks = 0; ks < 32; ks += 16) {
            uint32_t ahi[2][4], alo[2][4];
            #pragma unroll
            for (int mt = 0; mt < 2; mt++) {
                int eoff = (wm * 32 + mt * 16 + arow) * LPAD + ks + acol8;
                ldsm_x4(ahi[mt], b + LO_AHI + eoff * 2);
                ldsm_x4(alo[mt], b + LO_ALO + eoff * 2);
            }
            #pragma unroll
            for (int nt = 0; nt < 8; nt++) {
                int eoff = (wn * 64 + nt * 8 + brow) * LPAD + ks + bcol8;
                uint32_t bhi[2], blo[2];
                ldsm_x2(bhi, b + LO_BHI + eoff * 2);
                ldsm_x2(blo, b + LO_BLO + eoff * 2);
                #pragma unroll
                for (int mt = 0; mt < 2; mt++) {
                    mma_bf16(acc[mt][nt], ahi[mt], bhi);
                    mma_bf16(acc[mt][nt], ahi[mt], blo);
                    mma_bf16(acc[mt][nt], alo[mt], bhi);
                }
            }
        }
        __syncthreads();
    }

    const int erow = lane >> 2;
    const int ecol = (lane & 3) * 2;
    #pragma unroll
    for (int mt = 0; mt < 2; mt++) {
        #pragma unroll
        for (int nt = 0; nt < 8; nt++) {
            int col = bn0 + wn * 64 + nt * 8 + ecol;
            float b0 = __ldg(&bias[col]);
            float b1 = __ldg(&bias[col + 1]);
            size_t r0 = (size_t)(bm0 + wm * 32 + mt * 16 + erow);
            float2 v0 = make_float2(acc[mt][nt][0] + b0, acc[mt][nt][1] + b1);
            float2 v1 = make_float2(acc[mt][nt][2] + b0, acc[mt][nt][3] + b1);
            *(float2*)(C + r0 * OUT_DIM + col)       = v0;
            *(float2*)(C + (r0 + 8) * OUT_DIM + col) = v1;
        }
    }
}

// ---------------------------------------------------------------------------
extern "C" void kernel_launch(void* const* d_in, const int* in_sizes, int n_in,
                              void* d_out, int out_size)
{
    const float* x    = (const float*)d_in[0];
    const int*   ei   = (const int*)d_in[1];
    const float* ph   = (const float*)d_in[2];
    const float* Wg   = (const float*)d_in[3];     // [128][64] k-major
    const float* bg   = (const float*)d_in[4];
    const float* Wih  = (const float*)d_in[5];
    const float* Whh  = (const float*)d_in[6];
    const float* bih  = (const float*)d_in[7];
    const float* bhh  = (const float*)d_in[8];
    const float* Wlin = (const float*)d_in[9];
    const float* blin = (const float*)d_in[10];

    float* out    = (float*)d_out;
    float* logits = out;

    static float *p_xw = nullptr, *p_h = nullptr;
    static bool attr_done = false;
    if (!p_xw) {
        cudaGetSymbolAddress((void**)&p_xw, g_xw);
        cudaGetSymbolAddress((void**)&p_h,  g_h);
    }
    if (!attr_done) {
        cudaFuncSetAttribute(gru_mega_kernel,
                             cudaFuncAttributeMaxDynamicSharedMemorySize, GS_TOT);
        cudaFuncSetAttribute(logits_mma_kernel,
                             cudaFuncAttributeMaxDynamicSharedMemorySize, LG_TOT);
        attr_done = true;
    }

    const long long need = (long long)NUM_ENVS * (OUT_DIM + FLAT_DIM);
    float* hout = ((long long)out_size >= need)
                      ? out + (size_t)NUM_ENVS * OUT_DIM
                      : p_h;

    prep_kernel<<<128, 256>>>(Wih, Whh, bih, bhh);
    transpose_wg_kernel<<<32, 256>>>(Wg);
    split_wlin_kernel<<<(OUT_DIM * FLAT_DIM) / 256, 256>>>(Wlin);

    // 1) xw = x @ W_gcn via HMMA bf16-split
    xw_mma_kernel<<<N_NODES / 128, 256>>>(x, p_xw);

    // 2+3+4) scatter + GRU (HMMA) + gates fused
    gru_mega_kernel<<<N_NODES / 64, 256, GS_TOT>>>(p_xw, ei, bg, ph, hout);

    // 5) logits via mma.sync bf16-split GEMM (cp.async pipelined)
    {
        dim3 g(NUM_ENVS / 128, OUT_DIM / 128);
        logits_mma_kernel<<<g, 256, LG_TOT>>>(logits, blin);
    }
}

// round 15
// speedup vs baseline: 1.5268x; 1.1809x over previous
#include <cuda_runtime.h>
#include <cuda_bf16.h>
#include <math.h>
#include <cstdint>

// Problem constants
#define NUM_ENVS   16384
#define NUM_AGENTS 16
#define IN_DIM     128
#define GCN_H      64
#define RNN_H      64
#define E_PER_G    128
#define OUT_DIM    512
#define FLAT_DIM   1024
#define N_NODES    ((size_t)NUM_ENVS * NUM_AGENTS)   // 262144

typedef unsigned long long u64;

// ---- device scratch (static) ----------------------------------------------
__device__ float g_xw  [N_NODES * GCN_H];      // x @ W_gcn (fp32)
__device__ float g_h   [N_NODES * RNN_H];      // h_new fallback
__device__ float g_bias2[256];
__device__ __nv_bfloat16 g_B2hi[256 * 128];    // fused GRU weights [n][k] hi
__device__ __nv_bfloat16 g_B2lo[256 * 128];    // fused GRU weights [n][k] lo
__device__ __nv_bfloat16 g_Wghi[64 * 128];     // W_gcn^T [n][k] hi
__device__ __nv_bfloat16 g_Wglo[64 * 128];     // W_gcn^T [n][k] lo
__device__ __nv_bfloat16 g_Ahi[N_NODES * RNN_H];   // h_new bf16 hi
__device__ __nv_bfloat16 g_Alo[N_NODES * RNN_H];   // h_new bf16 lo
__device__ __nv_bfloat16 g_Whi[(size_t)OUT_DIM * FLAT_DIM]; // W_lin bf16 hi
__device__ __nv_bfloat16 g_Wlo[(size_t)OUT_DIM * FLAT_DIM]; // W_lin bf16 lo

__device__ __forceinline__ uint32_t smem_u32(const void* p) {
    uint32_t a;
    asm("{ .reg .u64 t; cvta.to.shared.u64 t, %1; cvt.u32.u64 %0, t; }"
        : "=r"(a) : "l"(p));
    return a;
}

// ---- mma.sync / ldmatrix / cp.async helpers (validated R12-R14) ------------
__device__ __forceinline__ void ldsm_x4(uint32_t* r, uint32_t addr) {
    asm volatile("ldmatrix.sync.aligned.m8n8.x4.shared.b16 {%0,%1,%2,%3}, [%4];"
        : "=r"(r[0]), "=r"(r[1]), "=r"(r[2]), "=r"(r[3]) : "r"(addr));
}
__device__ __forceinline__ void ldsm_x2(uint32_t* r, uint32_t addr) {
    asm volatile("ldmatrix.sync.aligned.m8n8.x2.shared.b16 {%0,%1}, [%2];"
        : "=r"(r[0]), "=r"(r[1]) : "r"(addr));
}
__device__ __forceinline__ void mma_bf16(float* d, const uint32_t* a,
                                         const uint32_t* b) {
    asm volatile("mma.sync.aligned.m16n8k16.row.col.f32.bf16.bf16.f32 "
        "{%0,%1,%2,%3}, {%4,%5,%6,%7}, {%8,%9}, {%0,%1,%2,%3};"
        : "+f"(d[0]), "+f"(d[1]), "+f"(d[2]), "+f"(d[3])
        : "r"(a[0]), "r"(a[1]), "r"(a[2]), "r"(a[3]), "r"(b[0]), "r"(b[1]));
}
__device__ __forceinline__ void cp16(uint32_t dst, const void* src) {
    asm volatile("cp.async.ca.shared.global [%0], [%1], 16;"
                 :: "r"(dst), "l"(src));
}
#define CP_COMMIT() asm volatile("cp.async.commit_group;" ::: "memory")
#define CP_WAIT(n)  asm volatile("cp.async.wait_group %0;" :: "n"(n) : "memory")

__device__ __forceinline__ uint32_t pack_bf2(float a, float b) {
    __nv_bfloat16 ha = __float2bfloat16(a);
    __nv_bfloat16 hb = __float2bfloat16(b);
    return (uint32_t)__bfloat16_as_ushort(ha)
         | ((uint32_t)__bfloat16_as_ushort(hb) << 16);
}

// ---------------------------------------------------------------------------
// Prep (parallel): fused GRU weights bf16 hi/lo [n][k] + bias2.
// cols n: 0..63 r, 64..127 z, 128..191 n_x, 192..255 n_h. k: [gcn|h].
// ---------------------------------------------------------------------------
__global__ void prep_kernel(const float* __restrict__ Wih,
                            const float* __restrict__ Whh,
                            const float* __restrict__ bih,
                            const float* __restrict__ bhh)
{
    const int idx = blockIdx.x * 256 + threadIdx.x;   // 0..32767
    const int n = idx >> 7, k = idx & 127;
    float v;
    if (k < 64) {
        v = (n < 192) ? Wih[n * 64 + k] : 0.0f;
    } else {
        int kk = k - 64;
        if      (n < 128) v = Whh[n * 64 + kk];
        else if (n < 192) v = 0.0f;
        else              v = Whh[(n - 64) * 64 + kk];
    }
    __nv_bfloat16 hi = __float2bfloat16(v);
    g_B2hi[idx] = hi;
    g_B2lo[idx] = __float2bfloat16(v - __bfloat162float(hi));
    if (k == 0) {
        if (n < 128)      g_bias2[n] = bih[n] + bhh[n];
        else if (n < 192) g_bias2[n] = bih[n];
        else              g_bias2[n] = bhh[n - 64];
    }
}

// W_gcn [128][64] k-major -> bf16 hi/lo [64 n][128 k]
__global__ void transpose_wg_kernel(const float* __restrict__ Wg)
{
    const int idx = blockIdx.x * 256 + threadIdx.x;   // 0..8191
    const int n = idx >> 7, k = idx & 127;
    float v = Wg[k * 64 + n];
    __nv_bfloat16 hi = __float2bfloat16(v);
    g_Wghi[idx] = hi;
    g_Wglo[idx] = __float2bfloat16(v - __bfloat162float(hi));
}

// Split W_lin [512][1024] fp32 -> bf16 hi + lo (residual)
__global__ void split_wlin_kernel(const float* __restrict__ Wlin)
{
    const int idx = blockIdx.x * 256 + threadIdx.x;
    float w = Wlin[idx];
    __nv_bfloat16 hi = __float2bfloat16(w);
    g_Whi[idx] = hi;
    g_Wlo[idx] = __float2bfloat16(w - __bfloat162float(hi));
}

// ---------------------------------------------------------------------------
// xw = x @ W_gcn via HMMA bf16-split (unchanged from R14, passing).
// ---------------------------------------------------------------------------
#define XAPAD 40
#define XBPAD 136

__global__ __launch_bounds__(256)
void xw_mma_kernel(const float* __restrict__ x, float* __restrict__ xwout)
{
    __shared__ __nv_bfloat16 sAhi[128 * XAPAD];
    __shared__ __nv_bfloat16 sAlo[128 * XAPAD];
    __shared__ __nv_bfloat16 sBhi[64 * XBPAD];
    __shared__ __nv_bfloat16 sBlo[64 * XBPAD];

    const int tid  = threadIdx.x;
    const int wid  = tid >> 5;
    const int lane = tid & 31;
    const int bm0 = blockIdx.x * 128;

    const uint32_t aAhi = smem_u32(sAhi);
    const uint32_t aAlo = smem_u32(sAlo);
    const uint32_t aBhi = smem_u32(sBhi);
    const uint32_t aBlo = smem_u32(sBlo);

    #pragma unroll
    for (int t = 0; t < 4; t++) {
        int idx = tid + 256 * t;
        int row = idx >> 4, q = idx & 15;
        *(uint4*)&sBhi[row * XBPAD + q * 8] = *(const uint4*)(g_Wghi + row * 128 + q * 8);
        *(uint4*)&sBlo[row * XBPAD + q * 8] = *(const uint4*)(g_Wglo + row * 128 + q * 8);
    }

    float acc[8][4];
    #pragma unroll
    for (int nt = 0; nt < 8; nt++)
        #pragma unroll
        for (int q = 0; q < 4; q++) acc[nt][q] = 0.0f;

    const int arow = (lane & 15);
    const int acol8 = (lane >> 4) * 8;
    const int brow = (lane & 7);
    const int bcol8 = ((lane >> 3) & 1) * 8;

    for (int kb = 0; kb < 128; kb += 32) {
        #pragma unroll
        for (int t = 0; t < 4; t++) {
            int idx = tid + 256 * t;
            int row = idx >> 3, q = idx & 7;
            float4 v = __ldg((const float4*)(x + (size_t)(bm0 + row) * 128 + kb + q * 4));
            int base = row * XAPAD + q * 4;
            *(uint32_t*)&sAhi[base]     = pack_bf2(v.x, v.y);
            *(uint32_t*)&sAhi[base + 2] = pack_bf2(v.z, v.w);
            float rx = v.x - __bfloat162float(__float2bfloat16(v.x));
            float ry = v.y - __bfloat162float(__float2bfloat16(v.y));
            float rz = v.z - __bfloat162float(__float2bfloat16(v.z));
            float rw = v.w - __bfloat162float(__float2bfloat16(v.w));
            *(uint32_t*)&sAlo[base]     = pack_bf2(rx, ry);
            *(uint32_t*)&sAlo[base + 2] = pack_bf2(rz, rw);
        }
        __syncthreads();

        #pragma unroll
        for (int ks = 0; ks < 32; ks += 16) {
            uint32_t ahi[4], alo[4];
            int eoffA = (wid * 16 + arow) * XAPAD + ks + acol8;
            ldsm_x4(ahi, aAhi + eoffA * 2);
            ldsm_x4(alo, aAlo + eoffA * 2);
            #pragma unroll
            for (int nt = 0; nt < 8; nt++) {
                int eoffB = (nt * 8 + brow) * XBPAD + kb + ks + bcol8;
                uint32_t bhi[2], blo[2];
                ldsm_x2(bhi, aBhi + eoffB * 2);
                ldsm_x2(blo, aBlo + eoffB * 2);
                mma_bf16(acc[nt], ahi, bhi);
                mma_bf16(acc[nt], ahi, blo);
                mma_bf16(acc[nt], alo, bhi);
            }
        }
        __syncthreads();
    }

    const int erow = lane >> 2;
    const int ecol = (lane & 3) * 2;
    #pragma unroll
    for (int nt = 0; nt < 8; nt++) {
        int col = nt * 8 + ecol;
        size_t r0 = (size_t)(bm0 + wid * 16 + erow);
        *(float2*)(xwout + r0 * 64 + col)       = make_float2(acc[nt][0], acc[nt][1]);
        *(float2*)(xwout + (r0 + 8) * 64 + col) = make_float2(acc[nt][2], acc[nt][3]);
    }
}

// ---------------------------------------------------------------------------
// GRU mega v4: zero-block gate skip + packed smem/gmem stores.
// Block = 64 nodes (4 envs), 256 threads (8 warps).
// Mainloop phase 1 (k<64): gates {r,z,nx}; phase 2 (k>=64): {r,z,nh}.
// Dyn smem (101376 B): layout as R14.
// ---------------------------------------------------------------------------
#define GS_AHI 0
#define GS_ALO 17408
#define GS_BHI 34816
#define GS_BLO 55296
#define GS_SXW 75776
#define GS_ADJ 92672
#define GS_DEG 97024
#define GS_SED 97280
#define GS_TOT 101376
#define APAD 136
#define BPAD 40

__global__ __launch_bounds__(256, 2)
void gru_mega_kernel(const float* __restrict__ xw,
                     const int* __restrict__ ei,
                     const float* __restrict__ bg,
                     const float* __restrict__ ph,
                     float* __restrict__ hout)
{
    extern __shared__ __align__(16) char gsm[];
    __nv_bfloat16* sAhi = (__nv_bfloat16*)(gsm + GS_AHI);
    __nv_bfloat16* sAlo = (__nv_bfloat16*)(gsm + GS_ALO);
    __nv_bfloat16* sBhi = (__nv_bfloat16*)(gsm + GS_BHI);
    __nv_bfloat16* sBlo = (__nv_bfloat16*)(gsm + GS_BLO);
    float* sxw = (float*)(gsm + GS_SXW);
    float* adj = (float*)(gsm + GS_ADJ);
    float* deg = (float*)(gsm + GS_DEG);
    int*   sed = (int*)  (gsm + GS_SED);

    const int tid  = threadIdx.x;
    const int bm   = blockIdx.x * 64;
    const int env0 = blockIdx.x * 4;
    const int w    = tid >> 5;
    const int lane = tid & 31;

    const uint32_t gsb  = smem_u32(gsm);
    const uint32_t aA_hi = gsb + GS_AHI;
    const uint32_t aA_lo = gsb + GS_ALO;
    const uint32_t aB_hi = gsb + GS_BHI;
    const uint32_t aB_lo = gsb + GS_BLO;

    // ---- prefetch B chunk 0 (rows < 192 only; nh rows are zero for k<64) ---
    #pragma unroll
    for (int t = 0; t < 4; t++) {
        int idx = tid + 256 * t;                 // 0..1023
        int n = idx >> 2, q = idx & 3;
        if (n < 192) {
            uint32_t so = n * (BPAD * 2) + q * 16;
            cp16(aB_hi + so, g_B2hi + (size_t)n * 128 + q * 8);
            cp16(aB_lo + so, g_B2lo + (size_t)n * 128 + q * 8);
        }
    }
    CP_COMMIT();

    // ---- edges + stage xw^T (fp32) + stage ph into A cols 64..127 ----------
    #pragma unroll
    for (int t = 0; t < 4; t++) {
        int idx = tid + 256 * t;
        sed[idx] = __ldg(&ei[(size_t)env0 * 2 * E_PER_G + idx]) & 15;
    }
    #pragma unroll
    for (int t = 0; t < 4; t++) {
        int idx = tid + 256 * t;                 // 0..1023
        int row = idx >> 4, q = idx & 15;
        float4 v = __ldg((const float4*)(xw + (size_t)(bm + row) * 64 + q * 4));
        sxw[(4 * q + 0) * 66 + row] = v.x;
        sxw[(4 * q + 1) * 66 + row] = v.y;
        sxw[(4 * q + 2) * 66 + row] = v.z;
        sxw[(4 * q + 3) * 66 + row] = v.w;
    }
    #pragma unroll
    for (int t = 0; t < 4; t++) {
        int idx = tid + 256 * t;                 // 0..1023
        int row = idx >> 4, q = idx & 15;        // col = 64 + 4q
        float4 v = __ldg((const float4*)(ph + (size_t)(bm + row) * 64 + 4 * q));
        int base = row * APAD + 64 + 4 * q;
        *(uint32_t*)&sAhi[base]     = pack_bf2(v.x, v.y);
        *(uint32_t*)&sAhi[base + 2] = pack_bf2(v.z, v.w);
        float rx = v.x - __bfloat162float(__float2bfloat16(v.x));
        float ry = v.y - __bfloat162float(__float2bfloat16(v.y));
        float rz = v.z - __bfloat162float(__float2bfloat16(v.z));
        float rw = v.w - __bfloat162float(__float2bfloat16(v.w));
        *(uint32_t*)&sAlo[base]     = pack_bf2(rx, ry);
        *(uint32_t*)&sAlo[base + 2] = pack_bf2(rz, rw);
    }
    if (tid < 64) deg[tid] = 1.0f;
    #pragma unroll
    for (int t = 0; t < 5; t++) {
        int i = tid + 256 * t;
        if (i < 4 * 16 * 17) adj[i] = 0.0f;
    }
    __syncthreads();

    // ---- degrees -----------------------------------------------------------
    #pragma unroll
    for (int t = 0; t < 2; t++) {
        int eidx = tid + 256 * t;
        int e = eidx >> 7, p = eidx & 127;
        atomicAdd(&deg[e * 16 + sed[e * 256 + 128 + p]], 1.0f);
    }
    __syncthreads();

    // ---- adjacency (normalized) + self-loop --------------------------------
    #pragma unroll
    for (int t = 0; t < 2; t++) {
        int eidx = tid + 256 * t;
        int e = eidx >> 7, p = eidx & 127;
        int row = sed[e * 256 + p];
        int col = sed[e * 256 + 128 + p];
        float nm = rsqrtf(deg[e * 16 + row] * deg[e * 16 + col]);
        atomicAdd(&adj[(e * 16 + col) * 17 + row], nm);
    }
    if (tid < 64) {
        int e = tid >> 4, a = tid & 15;
        atomicAdd(&adj[(e * 16 + a) * 17 + a], 1.0f / deg[tid]);
    }
    __syncthreads();

    // ---- gcn = Adj @ xw + bias -> A cols 0..63 (packed bf16 hi/lo) ---------
    {
        const int a_loc = tid & 63;
        const int jq = tid >> 6;                 // 0..3
        const int e = a_loc >> 4, a = a_loc & 15;
        float wrow[16];
        #pragma unroll
        for (int b = 0; b < 16; b++)
            wrow[b] = adj[(e * 16 + a) * 17 + b];
        #pragma unroll
        for (int jj = 0; jj < 16; jj += 2) {
            int j0 = jq * 16 + jj;
            float a0 = __ldg(&bg[j0]);
            float a1 = __ldg(&bg[j0 + 1]);
            #pragma unroll
            for (int b = 0; b < 16; b++) {
                float xv = sxw[j0 * 66 + e * 16 + b];
                float yv = sxw[(j0 + 1) * 66 + e * 16 + b];
                a0 += wrow[b] * xv;
                a1 += wrow[b] * yv;
            }
            int base = a_loc * APAD + j0;
            *(uint32_t*)&sAhi[base] = pack_bf2(a0, a1);
            float r0 = a0 - __bfloat162float(__float2bfloat16(a0));
            float r1 = a1 - __bfloat162float(__float2bfloat16(a1));
            *(uint32_t*)&sAlo[base] = pack_bf2(r0, r1);
        }
    }

    // ---- HMMA mainloop -----------------------------------------------------
    float acc[4][4][4];   // [m16 tile][gate][frag]
    #pragma unroll
    for (int mt = 0; mt < 4; mt++)
        #pragma unroll
        for (int gt = 0; gt < 4; gt++)
            #pragma unroll
            for (int q = 0; q < 4; q++) acc[mt][gt][q] = 0.0f;

    const int arow = (lane & 15);
    const int acol8 = (lane >> 4) * 8;
    const int brow = (lane & 7);
    const int bcol8 = ((lane >> 3) & 1) * 8;

    // phase 1: k in [0,64), gates {0=r, 1=z, 2=nx}
    for (int kb = 0; kb < 64; kb += 32) {
        if (kb == 0) {
            CP_WAIT(0);
        } else {
            #pragma unroll
            for (int t = 0; t < 4; t++) {
                int idx = tid + 256 * t;
                int n = idx >> 2, q = idx & 3;
                if (n < 192) {
                    int soff = n * BPAD + q * 8;
                    size_t goff = (size_t)n * 128 + kb + q * 8;
                    *(uint4*)&sBhi[soff] = *(const uint4*)(g_B2hi + goff);
                    *(uint4*)&sBlo[soff] = *(const uint4*)(g_B2lo + goff);
                }
            }
        }
        __syncthreads();

        #pragma unroll
        for (int ks = 0; ks < 32; ks += 16) {
            uint32_t bhi[3][2], blo[3][2];
            #pragma unroll
            for (int gt = 0; gt < 3; gt++) {
                int eoff = ((w + 8 * gt) * 8 + brow) * BPAD + ks + bcol8;
                ldsm_x2(bhi[gt], aB_hi + eoff * 2);
                ldsm_x2(blo[gt], aB_lo + eoff * 2);
            }
            #pragma unroll
            for (int mt = 0; mt < 4; mt++) {
                uint32_t ahi[4], alo[4];
                int eoff = (mt * 16 + arow) * APAD + kb + ks + acol8;
                ldsm_x4(ahi, aA_hi + eoff * 2);
                ldsm_x4(alo, aA_lo + eoff * 2);
                #pragma unroll
                for (int gt = 0; gt < 3; gt++) {
                    mma_bf16(acc[mt][gt], ahi, bhi[gt]);
                    mma_bf16(acc[mt][gt], ahi, blo[gt]);
                    mma_bf16(acc[mt][gt], alo, bhi[gt]);
                }
            }
        }
        __syncthreads();
    }

    // phase 2: k in [64,128), gates {0=r, 1=z, 3=nh}
    for (int kb = 64; kb < 128; kb += 32) {
        #pragma unroll
        for (int t = 0; t < 4; t++) {
            int idx = tid + 256 * t;
            int n = idx >> 2, q = idx & 3;
            if (n < 128 || n >= 192) {
                int soff = n * BPAD + q * 8;
                size_t goff = (size_t)n * 128 + kb + q * 8;
                *(uint4*)&sBhi[soff] = *(const uint4*)(g_B2hi + goff);
                *(uint4*)&sBlo[soff] = *(const uint4*)(g_B2lo + goff);
            }
        }
        __syncthreads();

        #pragma unroll
        for (int ks = 0; ks < 32; ks += 16) {
            uint32_t bhi[3][2], blo[3][2];
            #pragma unroll
            for (int gg = 0; gg < 3; gg++) {
                int gt = (gg < 2) ? gg : 3;
                int eoff = ((w + 8 * gt) * 8 + brow) * BPAD + ks + bcol8;
                ldsm_x2(bhi[gg], aB_hi + eoff * 2);
                ldsm_x2(blo[gg], aB_lo + eoff * 2);
            }
            #pragma unroll
            for (int mt = 0; mt < 4; mt++) {
                uint32_t ahi[4], alo[4];
                int eoff = (mt * 16 + arow) * APAD + kb + ks + acol8;
                ldsm_x4(ahi, aA_hi + eoff * 2);
                ldsm_x4(alo, aA_lo + eoff * 2);
                #pragma unroll
                for (int gg = 0; gg < 3; gg++) {
                    int gt = (gg < 2) ? gg : 3;
                    mma_bf16(acc[mt][gt], ahi, bhi[gg]);
                    mma_bf16(acc[mt][gt], ahi, blo[gg]);
                    mma_bf16(acc[mt][gt], alo, bhi[gg]);
                }
            }
        }
        __syncthreads();
    }

    // ---- gate epilogue (packed stores; cols c0/c0+1 share a row) -----------
    const int c0 = 8 * w + (lane & 3) * 2;
    const float br0 = __ldg(&g_bias2[c0]),       br1 = __ldg(&g_bias2[c0 + 1]);
    const float bz0 = __ldg(&g_bias2[64 + c0]),  bz1 = __ldg(&g_bias2[64 + c0 + 1]);
    const float bx0 = __ldg(&g_bias2[128 + c0]), bx1 = __ldg(&g_bias2[128 + c0 + 1]);
    const float bh0 = __ldg(&g_bias2[192 + c0]), bh1 = __ldg(&g_bias2[192 + c0 + 1]);
    #pragma unroll
    for (int mt = 0; mt < 4; mt++) {
        #pragma unroll
        for (int qp = 0; qp < 2; qp++) {         // q pair (2qp, 2qp+1)
            const int row = mt * 16 + (lane >> 2) + (qp ? 8 : 0);
            const size_t node = (size_t)bm + row;
            const int q0 = 2 * qp, q1 = 2 * qp + 1;
            float rp0 = acc[mt][0][q0] + br0, rp1 = acc[mt][0][q1] + br1;
            float zp0 = acc[mt][1][q0] + bz0, zp1 = acc[mt][1][q1] + bz1;
            float nx0 = acc[mt][2][q0] + bx0, nx1 = acc[mt][2][q1] + bx1;
            float nh0 = acc[mt][3][q0] + bh0, nh1 = acc[mt][3][q1] + bh1;
            float r0 = 1.0f / (1.0f + expf(-rp0));
            float r1 = 1.0f / (1.0f + expf(-rp1));
            float z0 = 1.0f / (1.0f + expf(-zp0));
            float z1 = 1.0f / (1.0f + expf(-zp1));
            float n0 = tanhf(nx0 + r0 * nh0);
            float n1 = tanhf(nx1 + r1 * nh1);
            float2 hp = *(const float2*)(ph + node * 64 + c0);
            float hv0 = (1.0f - z0) * n0 + z0 * hp.x;
            float hv1 = (1.0f - z1) * n1 + z1 * hp.y;
            *(float2*)(hout + node * 64 + c0) = make_float2(hv0, hv1);
            *(uint32_t*)&g_Ahi[node * 64 + c0] = pack_bf2(hv0, hv1);
            float l0 = hv0 - __bfloat162float(__float2bfloat16(hv0));
            float l1 = hv1 - __bfloat162float(__float2bfloat16(hv1));
            *(uint32_t*)&g_Alo[node * 64 + c0] = pack_bf2(l0, l1);
        }
    }
}

// ---------------------------------------------------------------------------
// Logits via mma.sync bf16-split GEMM, 2-stage cp.async (unchanged, passing).
// ---------------------------------------------------------------------------
#define LPAD 40
#define LG_STG 40960
#define LO_AHI 0
#define LO_ALO 10240
#define LO_BHI 20480
#define LO_BLO 30720
#define LG_TOT 81920

__global__ __launch_bounds__(256)
void logits_mma_kernel(float* __restrict__ C, const float* __restrict__ bias)
{
    extern __shared__ __align__(16) char lsm[];
    const uint32_t sbase = smem_u32(lsm);

    const int tid  = threadIdx.x;
    const int wid  = tid >> 5;
    const int lane = tid & 31;
    const int wm = wid >> 1;
    const int wn = wid & 1;
    const int bm0 = blockIdx.x * 128;
    const int bn0 = blockIdx.y * 128;

    float acc[2][8][4];
    #pragma unroll
    for (int mt = 0; mt < 2; mt++)
        #pragma unroll
        for (int nt = 0; nt < 8; nt++)
            #pragma unroll
            for (int q = 0; q < 4; q++) acc[mt][nt][q] = 0.0f;

    const int arow = (lane & 15);
    const int acol8 = (lane >> 4) * 8;
    const int brow = (lane & 7);
    const int bcol8 = ((lane >> 3) & 1) * 8;

    const int srow = tid >> 2;
    const int sq   = tid & 3;

    {
        uint32_t base = sbase;
        #pragma unroll
        for (int t = 0; t < 2; t++) {
            int row = srow + 64 * t;
            uint32_t so = row * (LPAD * 2) + sq * 16;
            size_t ga = (size_t)(bm0 + row) * FLAT_DIM + sq * 8;
            size_t gb = (size_t)(bn0 + row) * FLAT_DIM + sq * 8;
            cp16(base + LO_AHI + so, g_Ahi + ga);
            cp16(base + LO_ALO + so, g_Alo + ga);
            cp16(base + LO_BHI + so, g_Whi + gb);
            cp16(base + LO_BLO + so, g_Wlo + gb);
        }
        CP_COMMIT();
    }

    for (int i = 0; i < 32; i++) {
        if (i + 1 < 32) {
            uint32_t base = sbase + ((i + 1) & 1) * LG_STG;
            int kbn = (i + 1) * 32;
            #pragma unroll
            for (int t = 0; t < 2; t++) {
                int row = srow + 64 * t;
                uint32_t so = row * (LPAD * 2) + sq * 16;
                size_t ga = (size_t)(bm0 + row) * FLAT_DIM + kbn + sq * 8;
                size_t gb = (size_t)(bn0 + row) * FLAT_DIM + kbn + sq * 8;
                cp16(base + LO_AHI + so, g_Ahi + ga);
                cp16(base + LO_ALO + so, g_Alo + ga);
                cp16(base + LO_BHI + so, g_Whi + gb);
                cp16(base + LO_BLO + so, g_Wlo + gb);
            }
            CP_COMMIT();
            CP_WAIT(1);
        } else {
            CP_WAIT(0);
        }
        __syncthreads();

        const uint32_t b = sbase + (i & 1) * LG_STG;
        #pragma unroll
        for (int ks = 0; ks < 32; ks += 16) {
            uint32_t ahi[2][4], alo[2][4];
            #pragma unroll
            for (int mt = 0; mt < 2; mt++) {
                int eoff = (wm * 32 + mt * 16 + arow) * LPAD + ks + acol8;
                ldsm_x4(ahi[mt], b + LO_AHI + eoff * 2);
                ldsm_x4(alo[mt], b + LO_ALO + eoff * 2);
            }
            #pragma unroll
            for (int nt = 0; nt < 8; nt++) {
                int eoff = (wn * 64 + nt * 8 + brow) * LPAD + ks + bcol8;
                uint32_t bhi[2], blo[2];
                ldsm_x2(bhi, b + LO_BHI + eoff * 2);
                ldsm_x2(blo, b + LO_BLO + eoff * 2);
                #pragma unroll
                for (int mt = 0; mt < 2; mt++) {
                    mma_bf16(acc[mt][nt], ahi[mt], bhi);
                    mma_bf16(acc[mt][nt], ahi[mt], blo);
                    mma_bf16(acc[mt][nt], alo[mt], bhi);
                }
            }
        }
        __syncthreads();
    }

    const int erow = lane >> 2;
    const int ecol = (lane & 3) * 2;
    #pragma unroll
    for (int mt = 0; mt < 2; mt++) {
        #pragma unroll
        for (int nt = 0; nt < 8; nt++) {
            int col = bn0 + wn * 64 + nt * 8 + ecol;
            float b0 = __ldg(&bias[col]);
            float b1 = __ldg(&bias[col + 1]);
            size_t r0 = (size_t)(bm0 + wm * 32 + mt * 16 + erow);
            float2 v0 = make_float2(acc[mt][nt][0] + b0, acc[mt][nt][1] + b1);
            float2 v1 = make_float2(acc[mt][nt][2] + b0, acc[mt][nt][3] + b1);
            *(float2*)(C + r0 * OUT_DIM + col)       = v0;
            *(float2*)(C + (r0 + 8) * OUT_DIM + col) = v1;
        }
    }
}

// ---------------------------------------------------------------------------
extern "C" void kernel_launch(void* const* d_in, const int* in_sizes, int n_in,
                              void* d_out, int out_size)
{
    const float* x    = (const float*)d_in[0];
    const int*   ei   = (const int*)d_in[1];
    const float* ph   = (const float*)d_in[2];
    const float* Wg   = (const float*)d_in[3];     // [128][64] k-major
    const float* bg   = (const float*)d_in[4];
    const float* Wih  = (const float*)d_in[5];
    const float* Whh  = (const float*)d_in[6];
    const float* bih  = (const float*)d_in[7];
    const float* bhh  = (const float*)d_in[8];
    const float* Wlin = (const float*)d_in[9];
    const float* blin = (const float*)d_in[10];

    float* out    = (float*)d_out;
    float* logits = out;

    static float *p_xw = nullptr, *p_h = nullptr;
    static bool attr_done = false;
    if (!p_xw) {
        cudaGetSymbolAddress((void**)&p_xw, g_xw);
        cudaGetSymbolAddress((void**)&p_h,  g_h);
    }
    if (!attr_done) {
        cudaFuncSetAttribute(gru_mega_kernel,
                             cudaFuncAttributeMaxDynamicSharedMemorySize, GS_TOT);
        cudaFuncSetAttribute(logits_mma_kernel,
                             cudaFuncAttributeMaxDynamicSharedMemorySize, LG_TOT);
        attr_done = true;
    }

    const long long need = (long long)NUM_ENVS * (OUT_DIM + FLAT_DIM);
    float* hout = ((long long)out_size >= need)
                      ? out + (size_t)NUM_ENVS * OUT_DIM
                      : p_h;

    prep_kernel<<<128, 256>>>(Wih, Whh, bih, bhh);
    transpose_wg_kernel<<<32, 256>>>(Wg);
    split_wlin_kernel<<<(OUT_DIM * FLAT_DIM) / 256, 256>>>(Wlin);

    // 1) xw = x @ W_gcn via HMMA bf16-split
    xw_mma_kernel<<<N_NODES / 128, 256>>>(x, p_xw);

    // 2+3+4) scatter + GRU (HMMA, zero-gate skip) + gates fused
    gru_mega_kernel<<<N_NODES / 64, 256, GS_TOT>>>(p_xw, ei, bg, ph, hout);

    // 5) logits via mma.sync bf16-split GEMM (cp.async pipelined)
    {
        dim3 g(NUM_ENVS / 128, OUT_DIM / 128);
        logits_mma_kernel<<<g, 256, LG_TOT>>>(logits, blin);
    }
}